// round 2
// baseline (speedup 1.0000x reference)
#include <cuda_runtime.h>
#include <cstdint>

// Fixed shapes from the reference
#define TT   16
#define HH   1280
#define WW   1280
#define NB   64
#define W4   (WW / 4)            // 320 float4 per row
#define HW4  (HH * W4)           // 409,600 float4 per frame
#define NTHR 256
#define NBLK (HW4 / NTHR)        // 1600 blocks

// Scratch (device globals — no allocations allowed)
__device__ double       g_acc   = 0.0;
__device__ unsigned int g_count = 0u;

// ---------------------------------------------------------------------------
// Single fused kernel:
//   1) stage boxes in shared, prefetch 8/16 frame loads (HBM busy immediately)
//   2) per-thread weights for its 4 x positions via box-interval overlap,
//      accumulated as 4 packed 8-bit counters (bit-spread multiply trick)
//   3) accumulate 16 frames, weighted dot, warp+block reduce
//   4) block atomicAdd(double); last block writes scalar out and resets state
// ---------------------------------------------------------------------------
__global__ void __launch_bounds__(NTHR) fused_kernel(const float* __restrict__ data,
                                                     const int*   __restrict__ boxes,
                                                     float* __restrict__ out) {
    __shared__ int4  sbox[NB];
    __shared__ float warp_sums[NTHR / 32];

    const int tid = threadIdx.x;
    const int gid = blockIdx.x * NTHR + tid;     // 0 .. HW4-1

    if (tid < NB) sbox[tid] = reinterpret_cast<const int4*>(boxes)[tid];

    const int y  = gid / W4;                     // mul-hi by constant
    const int x0 = (gid - y * W4) * 4;

    // --- prefetch first 8 frames so HBM is saturated during the mask loop ---
    const float4* p = reinterpret_cast<const float4*>(data) + gid;
    float4 v0 = __ldg(p + 0 * (size_t)HW4);
    float4 v1 = __ldg(p + 1 * (size_t)HW4);
    float4 v2 = __ldg(p + 2 * (size_t)HW4);
    float4 v3 = __ldg(p + 3 * (size_t)HW4);
    float4 v4 = __ldg(p + 4 * (size_t)HW4);
    float4 v5 = __ldg(p + 5 * (size_t)HW4);
    float4 v6 = __ldg(p + 6 * (size_t)HW4);
    float4 v7 = __ldg(p + 7 * (size_t)HW4);

    __syncthreads();   // sbox ready (loads above remain in flight)

    // --- per-thread weights: packed 4x8-bit counters in one u32 ---
    unsigned wpk = 0u;
#pragma unroll 4
    for (int n = 0; n < NB; n++) {
        int4 b = sbox[n];                        // x1, y1, x2, y2
        // y in [y1, y2) ?   (unsigned range trick)
        if ((unsigned)(y - b.y) >= (unsigned)(b.w - b.y)) continue;
        int lo = max(b.x - x0, 0);
        int hi = min(b.z - x0, 4);
        if (hi <= lo) continue;
        unsigned m = (1u << hi) - (1u << lo);    // 4-bit coverage of x0..x0+3
        wpk += (m * 0x00204081u) & 0x01010101u;  // spread bits -> byte counters
    }
    float w0 = (float)( wpk        & 0xFFu);
    float w1 = (float)((wpk >> 8)  & 0xFFu);
    float w2 = (float)((wpk >> 16) & 0xFFu);
    float w3 = (float)( wpk >> 24);

    // --- accumulate the 16 frames ---
    float a0, a1, a2, a3;
    a0 = ((v0.x + v1.x) + (v2.x + v3.x)) + ((v4.x + v5.x) + (v6.x + v7.x));
    a1 = ((v0.y + v1.y) + (v2.y + v3.y)) + ((v4.y + v5.y) + (v6.y + v7.y));
    a2 = ((v0.z + v1.z) + (v2.z + v3.z)) + ((v4.z + v5.z) + (v6.z + v7.z));
    a3 = ((v0.w + v1.w) + (v2.w + v3.w)) + ((v4.w + v5.w) + (v6.w + v7.w));
#pragma unroll
    for (int t = 8; t < TT; t++) {
        float4 v = __ldg(p + (size_t)t * HW4);
        a0 += v.x; a1 += v.y; a2 += v.z; a3 += v.w;
    }

    float s = fmaf(w0, a0, fmaf(w1, a1, fmaf(w2, a2, w3 * a3)));

    // --- warp reduce ---
#pragma unroll
    for (int off = 16; off > 0; off >>= 1)
        s += __shfl_down_sync(0xFFFFFFFFu, s, off);

    // --- block reduce ---
    const int lane = tid & 31;
    const int wid  = tid >> 5;
    if (lane == 0) warp_sums[wid] = s;
    __syncthreads();
    if (tid == 0) {
        float b = warp_sums[0];
#pragma unroll
        for (int i = 1; i < NTHR / 32; i++) b += warp_sums[i];

        atomicAdd(&g_acc, (double)b);
        __threadfence();
        unsigned old = atomicAdd(&g_count, 1u);
        if (old == NBLK - 1u) {
            __threadfence();                     // acquire all g_acc updates
            double total = atomicAdd(&g_acc, 0.0);
            out[0] = (float)total;
            g_acc = 0.0;                         // reset for next graph replay
            __threadfence();
            g_count = 0u;
        }
    }
}

extern "C" void kernel_launch(void* const* d_in, const int* in_sizes, int n_in,
                              void* d_out, int out_size) {
    const float* data  = (const float*)d_in[0];  // (16,1280,1280) fp32
    const int*   boxes = (const int*)d_in[1];    // (64,4) int32 [x1,y1,x2,y2]
    float*       out   = (float*)d_out;

    fused_kernel<<<NBLK, NTHR>>>(data, boxes, out);
}

// round 3
// speedup vs baseline: 1.3378x; 1.3378x over previous
#include <cuda_runtime.h>
#include <cstdint>

// Fixed shapes
#define TT   16
#define HH   1280
#define WW   1280
#define NB   64
#define W4   (WW / 4)            // 320 float4 per row
#define HW4  (HH * W4)           // 409,600 float4 per frame
#define NTHR W4                  // 320 threads: one float4 (4 x) per thread
#define NBLK HH                  // one block per row
#define NWARP (NTHR / 32)        // 10 warps

__device__ double       g_acc   = 0.0;
__device__ unsigned int g_count = 0u;

// ---------------------------------------------------------------------------
// One block per image row y:
//  Phase A (cheap): box x-coverage weights for this row via shared difference
//    array (64 shared atomics for boxes whose [y1,y2) covers y) + block-wide
//    inclusive prefix scan over the 1280 columns.
//  Phase B: stream 16 frames of this row (float4/thread), weighted dot.
//  Phase C: block reduce -> atomicAdd(double); last block writes scalar + resets.
// ---------------------------------------------------------------------------
__global__ void __launch_bounds__(NTHR) fused_kernel(const float* __restrict__ data,
                                                     const int*   __restrict__ boxes,
                                                     float* __restrict__ out) {
    __shared__ int   sdiff[WW];          // difference array over columns
    __shared__ int   wsum[NWARP];        // per-warp scan totals
    __shared__ float warp_sums[NWARP];   // reduction

    const int tid  = threadIdx.x;        // 0..319
    const int y    = blockIdx.x;         // row
    const int lane = tid & 31;
    const int wid  = tid >> 5;

    // ---- prefetch 4 frames so HBM is busy during the mask phase ----
    const float4* p = reinterpret_cast<const float4*>(data) + (size_t)y * W4 + tid;
    float4 v0 = __ldg(p + 0 * (size_t)HW4);
    float4 v1 = __ldg(p + 1 * (size_t)HW4);
    float4 v2 = __ldg(p + 2 * (size_t)HW4);
    float4 v3 = __ldg(p + 3 * (size_t)HW4);

    // ---- Phase A: difference array ----
    for (int i = tid; i < WW; i += NTHR) sdiff[i] = 0;
    __syncthreads();

    if (tid < NB) {
        int4 b = __ldg(reinterpret_cast<const int4*>(boxes) + tid); // x1,y1,x2,y2
        if (b.y <= y && y < b.w) {
            atomicAdd(&sdiff[b.x],  1);
            atomicAdd(&sdiff[b.z], -1);   // x2 <= 1279 < WW
        }
    }
    __syncthreads();

    // per-thread 4-element local prefix (its columns 4*tid .. 4*tid+3)
    int4 c = reinterpret_cast<const int4*>(sdiff)[tid];
    int s0 = c.x, s1 = s0 + c.y, s2 = s1 + c.z, s3 = s2 + c.w;
    const int tot = s3;

    // warp-inclusive scan of per-thread totals
    int v = tot;
#pragma unroll
    for (int off = 1; off < 32; off <<= 1) {
        int n = __shfl_up_sync(0xFFFFFFFFu, v, off);
        if (lane >= off) v += n;
    }
    if (lane == 31) wsum[wid] = v;
    __syncthreads();

    int wprefix = 0;
#pragma unroll
    for (int i = 0; i < NWARP; i++)
        if (i < wid) wprefix += wsum[i];
    const int base = wprefix + (v - tot);      // exclusive prefix before this thread

    const float w0 = (float)(base + s0);
    const float w1 = (float)(base + s1);
    const float w2 = (float)(base + s2);
    const float w3 = (float)(base + s3);

    // ---- Phase B: accumulate 16 frames ----
    float a0 = (v0.x + v1.x) + (v2.x + v3.x);
    float a1 = (v0.y + v1.y) + (v2.y + v3.y);
    float a2 = (v0.z + v1.z) + (v2.z + v3.z);
    float a3 = (v0.w + v1.w) + (v2.w + v3.w);
#pragma unroll
    for (int t = 4; t < TT; t++) {
        float4 q = __ldg(p + (size_t)t * HW4);
        a0 += q.x; a1 += q.y; a2 += q.z; a3 += q.w;
    }

    float s = fmaf(w0, a0, fmaf(w1, a1, fmaf(w2, a2, w3 * a3)));

    // ---- Phase C: reduce + global accumulate ----
#pragma unroll
    for (int off = 16; off > 0; off >>= 1)
        s += __shfl_down_sync(0xFFFFFFFFu, s, off);
    if (lane == 0) warp_sums[wid] = s;
    __syncthreads();

    if (tid == 0) {
        float b = warp_sums[0];
#pragma unroll
        for (int i = 1; i < NWARP; i++) b += warp_sums[i];

        atomicAdd(&g_acc, (double)b);
        __threadfence();
        unsigned old = atomicAdd(&g_count, 1u);
        if (old == NBLK - 1u) {
            __threadfence();
            double total = atomicAdd(&g_acc, 0.0);
            out[0] = (float)total;
            g_acc = 0.0;                 // reset for next graph replay
            __threadfence();
            g_count = 0u;
        }
    }
}

extern "C" void kernel_launch(void* const* d_in, const int* in_sizes, int n_in,
                              void* d_out, int out_size) {
    const float* data  = (const float*)d_in[0];  // (16,1280,1280) fp32
    const int*   boxes = (const int*)d_in[1];    // (64,4) int32 [x1,y1,x2,y2]
    float*       out   = (float*)d_out;

    fused_kernel<<<NBLK, NTHR>>>(data, boxes, out);
}